// round 11
// baseline (speedup 1.0000x reference)
#include <cuda_runtime.h>

#define BATCH 128
#define HH 19
#define AA 5
#define CC 81
#define NN 361
#define NAA 1805
#define MM 24
#define ROWS 231040          // BATCH*NAA
#define EPSF 1e-7f

#define NBLK 444             // 148 SMs * 3 blocks
#define NTHR 256
#define WROWS 8              // rows per tile
#define WELEM (WROWS*CC)     // 648 floats = 2592 B (16B-divisible)
#define WF4   (WELEM/4)      // 162
#define NWT   (ROWS/WROWS)   // 28880 tiles
#define TOTW  (NBLK*NTHR/32) // 3552 warps
#define KBASE (NWT/TOTW)     // 8 tiles per warp
#define KREM  (NWT%TOTW)     // 464 warps get 9
#define SMEMB (8*3*WELEM*4)  // 62208 B: 8 warps x 3 ring buffers

// ---- device scratch (zero-init; reset by finishing block each call) ----
__device__ float g_Sce[NAA];
__device__ float g_cnt[NAA];
__device__ float g_corr[NAA];
__device__ float g_acc[8];        // 0 noobj_sub, 1 obj, 2 xy, 3 wh, 4 noobj_total
__device__ unsigned g_done;

__constant__ float c_aw[5] = {0.57273f, 1.87446f, 3.33843f, 7.88282f, 9.77052f};
__constant__ float c_ah[5] = {0.677385f, 2.06253f, 5.47434f, 3.52778f, 9.16828f};

__device__ __forceinline__ void cp16(unsigned s, const void* g) {
    asm volatile("cp.async.cg.shared.global [%0], [%1], 16;\n" :: "r"(s), "l"(g));
}
__device__ __forceinline__ void cpcommit() {
    asm volatile("cp.async.commit_group;\n" ::: "memory");
}

__global__ void __launch_bounds__(NTHR, 3)
yolo_loss_kernel(const float* __restrict__ conf,
                 const float* __restrict__ pred_xy,
                 const float* __restrict__ pred_wh,
                 const float* __restrict__ cls,
                 const float* __restrict__ tlabel,
                 const float* __restrict__ tobj,
                 float* __restrict__ out, int out_size) {
    extern __shared__ __align__(16) float dynsm[];   // [8][3][WELEM]
    __shared__ float s_no[NTHR / 32];
    __shared__ int   s_last;

    const int tid  = threadIdx.x;
    const int lane = tid & 31;
    const int wid  = tid >> 5;

    // ====== Phase 1: gt assignment (first 12 blocks = 3072 threads) ======
    if (blockIdx.x < (BATCH * MM) / NTHR) {
        const int gtid = blockIdx.x * NTHR + tid;
        const int b = gtid / MM;
        const float* to = tobj + (size_t)gtid * 4;
        float gx = to[0] * (1.f/32.f), gy = to[1] * (1.f/32.f);
        float gw = to[2] * (1.f/32.f), gh = to[3] * (1.f/32.f);
        int cell = (int)gy * HH + (int)gx;

        float bi = -1.f; int best = 0; unsigned overm = 0;
        #pragma unroll
        for (int a = 0; a < 5; a++) {
            float inter = fminf(c_aw[a], gw) * fminf(c_ah[a], gh);
            float iou = inter / (c_aw[a] * c_ah[a] + gw * gh - inter + EPSF);
            if (iou > 0.6f) overm |= (1u << a);
            if (iou > bi) { bi = iou; best = a; }
        }

        int base = (b * NN + cell) * AA;
        float pw = pred_wh[(size_t)(base + best) * 2];
        float ph = pred_wh[(size_t)(base + best) * 2 + 1];
        float inter = fminf(pw, gw) * fminf(ph, gh);
        float iou_pg = inter / (pw * ph + gw * gh - inter + EPSF);
        float sw = 2.f - (gw * (1.f/19.f)) * (gh * (1.f/19.f));

        float cp = fminf(fmaxf(conf[base + best], EPSF), 1.f - EPSF);
        float objc = -(iou_pg * __logf(cp) + (1.f - iou_pg) * __logf(1.f - cp));

        float px = pred_xy[(size_t)(base + best) * 2];
        float py = pred_xy[(size_t)(base + best) * 2 + 1];
        float xyc = sw * ((px - gx) * (px - gx) + (py - gy) * (py - gy));
        float whc = sw * ((pw - gw) * (pw - gw) + (ph - gh) * (ph - gh));

        const float* tl = tlabel + (size_t)gtid * CC;
        int lab = CC - 1;
        #pragma unroll 16
        for (int c = 0; c < CC - 1; c++)
            if (tl[c] > 0.5f) lab = c;

        float nsub = 0.f;
        #pragma unroll
        for (int a = 0; a < 5; a++) {
            if (a == best || ((overm >> a) & 1u)) {
                float ca = fminf(fmaxf(conf[base + a], EPSF), 1.f - EPSF);
                nsub += -__logf(1.f - ca);
                const float* crow = cls + (size_t)(base + a) * CC;
                atomicAdd(&g_corr[cell * AA + a], crow[CC - 1] - crow[lab]);
            }
        }
        atomicAdd(&g_cnt[cell * AA + best], 1.f);
        atomicAdd(&g_acc[0], nsub);
        atomicAdd(&g_acc[1], objc);
        atomicAdd(&g_acc[2], xyc);
        atomicAdd(&g_acc[3], whc);
    }

    // ====== Phase 2: contiguous per-warp tile runs, depth-3 cp.async ring ======
    const int gw = blockIdx.x * (NTHR / 32) + wid;            // 0..3551
    const int tbase = (gw < KREM) ? gw * (KBASE + 1)
                                  : KREM * (KBASE + 1) + (gw - KREM) * KBASE;
    const int tcnt  = (gw < KREM) ? (KBASE + 1) : KBASE;      // 9 or 8

    float* wsm = dynsm + wid * (3 * WELEM);
    const unsigned wsmb = (unsigned)__cvta_generic_to_shared(wsm);

    // prologue: issue copies for tiles 0 and 1 of this warp's run
    {
        const char* src = (const char*)(cls + (size_t)tbase * WELEM);
        #pragma unroll
        for (int i = lane; i < WF4; i += 32)
            cp16(wsmb + i * 16, src + (size_t)i * 16);
        cpcommit();
        const char* src1 = src + WELEM * 4;
        #pragma unroll
        for (int i = lane; i < WF4; i += 32)
            cp16(wsmb + WELEM * 4 + i * 16, src1 + (size_t)i * 16);
        cpcommit();
    }

    // conf noobj pass (overlaps in-flight copies)
    float nacc = 0.f;
    {
        const float4* c4 = (const float4*)conf;
        for (int i = blockIdx.x * NTHR + tid; i < ROWS / 4; i += NBLK * NTHR) {
            float4 v = c4[i];
            float p0 = fminf(fmaxf(v.x, EPSF), 1.f - EPSF);
            float p1 = fminf(fmaxf(v.y, EPSF), 1.f - EPSF);
            float p2 = fminf(fmaxf(v.z, EPSF), 1.f - EPSF);
            float p3 = fminf(fmaxf(v.w, EPSF), 1.f - EPSF);
            nacc -= __logf(1.f - p0) + __logf(1.f - p1)
                  + __logf(1.f - p2) + __logf(1.f - p3);
        }
    }

    const int r = lane >> 2;              // 0..7
    const int q = lane & 3;
    const int start = (q == 0) ? 0 : (20 * q + 1);    // 0,21,41,61

    int n0 = (tbase * WROWS) % NAA;       // row index mod NAA, then +8 per tile
    int bufoff = 0;                       // word offset of current ring slot

    for (int j = 0; j < tcnt; j++) {
        if (j + 2 < tcnt) {
            // issue tile j+2 into ring slot (j+2)%3
            int slot = j + 2; slot -= (slot >= 3) ? 3 : 0; slot -= (slot >= 3) ? 3 : 0;
            // (j+2) mod 3 for j<tcnt<=9: compute cheaply
            int s3 = (j + 2) % 3;
            const char* src = (const char*)(cls + (size_t)(tbase + j + 2) * WELEM);
            const unsigned dstb = wsmb + s3 * (WELEM * 4);
            #pragma unroll
            for (int i = lane; i < WF4; i += 32)
                cp16(dstb + i * 16, src + (size_t)i * 16);
            cpcommit();
            asm volatile("cp.async.wait_group 2;\n" ::: "memory");
        } else if (j + 1 < tcnt) {
            asm volatile("cp.async.wait_group 1;\n" ::: "memory");
        } else {
            asm volatile("cp.async.wait_group 0;\n" ::: "memory");
        }
        __syncwarp();

        {
            const float* rp = wsm + bufoff + r * CC + start;
            float a0 = 0.f, a1 = 0.f, a2 = 0.f, a3 = 0.f;
            #pragma unroll
            for (int i = 0; i < 20; i += 4) {
                a0 += __expf(rp[i]);
                a1 += __expf(rp[i + 1]);
                a2 += __expf(rp[i + 2]);
                a3 += __expf(rp[i + 3]);
            }
            float x80 = rp[19];                    // q==3: 61+19 = 80
            if (q == 0) a0 += __expf(rp[20]);
            float s = (a0 + a1) + (a2 + a3);
            s += __shfl_xor_sync(0xffffffffu, s, 1);
            s += __shfl_xor_sync(0xffffffffu, s, 2);
            if (q == 3) {
                int idx = n0 + r;
                if (idx >= NAA) idx -= NAA;
                atomicAdd(&g_Sce[idx], __logf(s) - x80);
            }
        }
        __syncwarp();
        bufoff += WELEM;
        if (bufoff == 3 * WELEM) bufoff = 0;
        n0 += WROWS;
        if (n0 >= NAA) n0 -= NAA;
    }

    // ====== block-reduce noobj partial, then last-block combine ======
    #pragma unroll
    for (int o = 16; o > 0; o >>= 1)
        nacc += __shfl_xor_sync(0xffffffffu, nacc, o);
    if (lane == 0) s_no[wid] = nacc;
    __syncthreads();
    if (tid == 0) {
        float tn = 0.f;
        #pragma unroll
        for (int i = 0; i < NTHR / 32; i++) tn += s_no[i];
        atomicAdd(&g_acc[4], tn);
        __threadfence();
        unsigned d = atomicAdd(&g_done, 1u);
        s_last = (d == (unsigned)(gridDim.x - 1)) ? 1 : 0;
    }
    __syncthreads();

    if (s_last) {
        __threadfence();
        float* red = dynsm;
        float p = 0.f;
        for (int n = tid; n < NAA; n += NTHR)
            p += g_cnt[n] * (g_Sce[n] + g_corr[n]);
        red[tid] = p;
        __syncthreads();
        for (int s2 = NTHR / 2; s2 > 0; s2 >>= 1) {
            if (tid < s2) red[tid] += red[tid + s2];
            __syncthreads();
        }
        if (tid == 0) {
            const float invB = 1.f / (float)BATCH;
            float noobj = (g_acc[4] - g_acc[0]) * invB;   // SCALE_NOOBJ = 1
            float obj   = 5.f * g_acc[1] * invB;
            float xy    = 5.f * g_acc[2] * invB;
            float wh    = 5.f * g_acc[3] * invB;
            float score = 5.f * red[0] * invB;
            float total = noobj + obj + xy + wh + score;
            out[0] = total;
            if (out_size >= 6) {
                out[1] = noobj; out[2] = obj; out[3] = score; out[4] = xy; out[5] = wh;
            }
        }
        __syncthreads();
        for (int n = tid; n < NAA; n += NTHR) {
            g_Sce[n] = 0.f; g_cnt[n] = 0.f; g_corr[n] = 0.f;
        }
        if (tid < 8) g_acc[tid] = 0.f;
        if (tid == 0) g_done = 0u;
        __threadfence();
    }
}

extern "C" void kernel_launch(void* const* d_in, const int* in_sizes, int n_in,
                              void* d_out, int out_size) {
    const float *conf = nullptr, *pxy = nullptr, *pwh = nullptr;
    const float *cls = nullptr, *tl = nullptr, *tobj = nullptr;
    for (int i = 0; i < n_in; i++) {
        int s = in_sizes[i];
        if (s == ROWS)                   conf = (const float*)d_in[i];
        else if (s == ROWS * 2)        { if (!pxy) pxy = (const float*)d_in[i];
                                         else      pwh = (const float*)d_in[i]; }
        else if (s == ROWS * CC)         cls  = (const float*)d_in[i];
        else if (s == BATCH * MM * CC)   tl   = (const float*)d_in[i];
        else if (s == BATCH * MM * 4)    tobj = (const float*)d_in[i];
    }
    cudaFuncSetAttribute(yolo_loss_kernel,
                         cudaFuncAttributeMaxDynamicSharedMemorySize, SMEMB);
    yolo_loss_kernel<<<NBLK, NTHR, SMEMB>>>(conf, pxy, pwh, cls, tl, tobj,
                                            (float*)d_out, out_size);
}

// round 12
// speedup vs baseline: 1.1722x; 1.1722x over previous
#include <cuda_runtime.h>

#define BATCH 128
#define HH 19
#define AA 5
#define CC 81
#define NN 361
#define NAA 1805
#define MM 24
#define ROWS 231040          // BATCH*NAA
#define NBOX (BATCH*MM)      // 3072
#define EPSF 1e-7f

#define NBLK 740             // 148 SMs * 5 blocks
#define NTHR 256
#define WROWS 8              // rows per tile
#define WELEM (WROWS*CC)     // 648 floats = 2592 B (16B-divisible)
#define WF4   (WELEM/4)      // 162
#define NWT   (ROWS/WROWS)   // 28880 tiles
#define TOTW  (NBLK*NTHR/32) // 5920 warps
#define KBASE (NWT/TOTW)     // 4
#define KREM  (NWT%TOTW)     // 5200 warps get 5 tiles
#define BBASE (NBOX/NBLK)    // 4 boxes per block
#define BREM  (NBOX%NBLK)    // first 112 blocks get 5

// ---- device scratch (zero-init; reset by finishing block each call) ----
__device__ float g_Sce[NAA];
__device__ float g_cnt[NAA];
__device__ float g_corr[NAA];
__device__ float g_acc[8];        // 0 noobj_sub, 1 obj, 2 xy, 3 wh, 4 noobj_total
__device__ unsigned g_done;

__constant__ float c_aw[5] = {0.57273f, 1.87446f, 3.33843f, 7.88282f, 9.77052f};
__constant__ float c_ah[5] = {0.677385f, 2.06253f, 5.47434f, 3.52778f, 9.16828f};

__device__ __forceinline__ void cp16(unsigned s, const void* g) {
    asm volatile("cp.async.cg.shared.global [%0], [%1], 16;\n" :: "r"(s), "l"(g));
}
__device__ __forceinline__ void cpcommit() {
    asm volatile("cp.async.commit_group;\n" ::: "memory");
}

__global__ void __launch_bounds__(NTHR, 5)
yolo_loss_kernel(const float* __restrict__ conf,
                 const float* __restrict__ pred_xy,
                 const float* __restrict__ pred_wh,
                 const float* __restrict__ cls,
                 const float* __restrict__ tlabel,
                 const float* __restrict__ tobj,
                 float* __restrict__ out, int out_size) {
    __shared__ __align__(16) float sm[NTHR / 32][2][WELEM];   // 41472 B
    __shared__ float s_no[NTHR / 32];
    __shared__ int   s_last;

    const int tid  = threadIdx.x;
    const int lane = tid & 31;
    const int wid  = tid >> 5;
    const int bx   = blockIdx.x;

    // ====== Phase 1: gt assignment, distributed over ALL blocks (4-5 boxes each) ======
    {
        const int bcnt  = (bx < BREM) ? (BBASE + 1) : BBASE;
        const int bbase = (bx < BREM) ? bx * (BBASE + 1)
                                      : BREM * (BBASE + 1) + (bx - BREM) * BBASE;
        if (tid < bcnt) {
            const int gtid = bbase + tid;
            const int b = gtid / MM;
            const float* to = tobj + (size_t)gtid * 4;
            float gx = to[0] * (1.f/32.f), gy = to[1] * (1.f/32.f);
            float gw = to[2] * (1.f/32.f), gh = to[3] * (1.f/32.f);
            int cell = (int)gy * HH + (int)gx;

            float bi = -1.f; int best = 0; unsigned overm = 0;
            #pragma unroll
            for (int a = 0; a < 5; a++) {
                float inter = fminf(c_aw[a], gw) * fminf(c_ah[a], gh);
                float iou = inter / (c_aw[a] * c_ah[a] + gw * gh - inter + EPSF);
                if (iou > 0.6f) overm |= (1u << a);
                if (iou > bi) { bi = iou; best = a; }
            }

            int base = (b * NN + cell) * AA;
            float pw = pred_wh[(size_t)(base + best) * 2];
            float ph = pred_wh[(size_t)(base + best) * 2 + 1];
            float inter = fminf(pw, gw) * fminf(ph, gh);
            float iou_pg = inter / (pw * ph + gw * gh - inter + EPSF);
            float sw = 2.f - (gw * (1.f/19.f)) * (gh * (1.f/19.f));

            float cp = fminf(fmaxf(conf[base + best], EPSF), 1.f - EPSF);
            float objc = -(iou_pg * __logf(cp) + (1.f - iou_pg) * __logf(1.f - cp));

            float px = pred_xy[(size_t)(base + best) * 2];
            float py = pred_xy[(size_t)(base + best) * 2 + 1];
            float xyc = sw * ((px - gx) * (px - gx) + (py - gy) * (py - gy));
            float whc = sw * ((pw - gw) * (pw - gw) + (ph - gh) * (ph - gh));

            const float* tl = tlabel + (size_t)gtid * CC;
            int lab = CC - 1;
            #pragma unroll 16
            for (int c = 0; c < CC - 1; c++)
                if (tl[c] > 0.5f) lab = c;

            float nsub = 0.f;
            #pragma unroll
            for (int a = 0; a < 5; a++) {
                if (a == best || ((overm >> a) & 1u)) {
                    float ca = fminf(fmaxf(conf[base + a], EPSF), 1.f - EPSF);
                    nsub += -__logf(1.f - ca);
                    const float* crow = cls + (size_t)(base + a) * CC;
                    atomicAdd(&g_corr[cell * AA + a], crow[CC - 1] - crow[lab]);
                }
            }
            atomicAdd(&g_cnt[cell * AA + best], 1.f);
            atomicAdd(&g_acc[0], nsub);
            atomicAdd(&g_acc[1], objc);
            atomicAdd(&g_acc[2], xyc);
            atomicAdd(&g_acc[3], whc);
        }
    }

    // ====== Phase 2: contiguous per-warp runs, depth-2 cp.async pipeline ======
    const int gw = bx * (NTHR / 32) + wid;                    // 0..5919
    const int tbase = (gw < KREM) ? gw * (KBASE + 1)
                                  : KREM * (KBASE + 1) + (gw - KREM) * KBASE;
    const int tcnt  = (gw < KREM) ? (KBASE + 1) : KBASE;      // 5 or 4

    const unsigned smb0 = (unsigned)__cvta_generic_to_shared(&sm[wid][0][0]);
    const unsigned smb1 = (unsigned)__cvta_generic_to_shared(&sm[wid][1][0]);

    // prologue: copy tile 0 of this warp's run into buf 0
    {
        const char* src = (const char*)(cls + (size_t)tbase * WELEM);
        #pragma unroll
        for (int i = lane; i < WF4; i += 32)
            cp16(smb0 + i * 16, src + (size_t)i * 16);
        cpcommit();
    }

    // conf noobj pass (<=1 float4 per thread; overlaps in-flight copy)
    float nacc = 0.f;
    {
        const float4* c4 = (const float4*)conf;
        for (int i = bx * NTHR + tid; i < ROWS / 4; i += NBLK * NTHR) {
            float4 v = c4[i];
            float p0 = fminf(fmaxf(v.x, EPSF), 1.f - EPSF);
            float p1 = fminf(fmaxf(v.y, EPSF), 1.f - EPSF);
            float p2 = fminf(fmaxf(v.z, EPSF), 1.f - EPSF);
            float p3 = fminf(fmaxf(v.w, EPSF), 1.f - EPSF);
            nacc -= __logf(1.f - p0) + __logf(1.f - p1)
                  + __logf(1.f - p2) + __logf(1.f - p3);
        }
    }

    const int r = lane >> 2;              // 0..7
    const int q = lane & 3;
    const int start = (q == 0) ? 0 : (20 * q + 1);    // 0,21,41,61

    int n0 = (tbase * WROWS) % NAA;       // row index mod NAA; +8 per tile

    for (int j = 0; j < tcnt; j++) {
        if (j + 1 < tcnt) {
            const char* src = (const char*)(cls + (size_t)(tbase + j + 1) * WELEM);
            const unsigned dstb = ((j + 1) & 1) ? smb1 : smb0;
            #pragma unroll
            for (int i = lane; i < WF4; i += 32)
                cp16(dstb + i * 16, src + (size_t)i * 16);
            cpcommit();
            asm volatile("cp.async.wait_group 1;\n" ::: "memory");
        } else {
            asm volatile("cp.async.wait_group 0;\n" ::: "memory");
        }
        __syncwarp();

        {
            const float* rp = &sm[wid][j & 1][r * CC + start];
            float a0 = 0.f, a1 = 0.f, a2 = 0.f, a3 = 0.f;
            #pragma unroll
            for (int i = 0; i < 20; i += 4) {
                a0 += __expf(rp[i]);
                a1 += __expf(rp[i + 1]);
                a2 += __expf(rp[i + 2]);
                a3 += __expf(rp[i + 3]);
            }
            float x80 = rp[19];                    // q==3: 61+19 = 80
            if (q == 0) a0 += __expf(rp[20]);
            float s = (a0 + a1) + (a2 + a3);
            s += __shfl_xor_sync(0xffffffffu, s, 1);
            s += __shfl_xor_sync(0xffffffffu, s, 2);
            if (q == 3) {
                int idx = n0 + r;
                if (idx >= NAA) idx -= NAA;
                atomicAdd(&g_Sce[idx], __logf(s) - x80);
            }
        }
        __syncwarp();
        n0 += WROWS;
        if (n0 >= NAA) n0 -= NAA;
    }

    // ====== block-reduce noobj partial, then last-block combine ======
    #pragma unroll
    for (int o = 16; o > 0; o >>= 1)
        nacc += __shfl_xor_sync(0xffffffffu, nacc, o);
    if (lane == 0) s_no[wid] = nacc;
    __syncthreads();
    if (tid == 0) {
        float tn = 0.f;
        #pragma unroll
        for (int i = 0; i < NTHR / 32; i++) tn += s_no[i];
        atomicAdd(&g_acc[4], tn);
        __threadfence();
        unsigned d = atomicAdd(&g_done, 1u);
        s_last = (d == (unsigned)(gridDim.x - 1)) ? 1 : 0;
    }
    __syncthreads();

    if (s_last) {
        __threadfence();
        float* red = &sm[0][0][0];
        float p = 0.f;
        for (int n = tid; n < NAA; n += NTHR)
            p += g_cnt[n] * (g_Sce[n] + g_corr[n]);
        red[tid] = p;
        __syncthreads();
        for (int s2 = NTHR / 2; s2 > 0; s2 >>= 1) {
            if (tid < s2) red[tid] += red[tid + s2];
            __syncthreads();
        }
        if (tid == 0) {
            const float invB = 1.f / (float)BATCH;
            float noobj = (g_acc[4] - g_acc[0]) * invB;   // SCALE_NOOBJ = 1
            float obj   = 5.f * g_acc[1] * invB;
            float xy    = 5.f * g_acc[2] * invB;
            float wh    = 5.f * g_acc[3] * invB;
            float score = 5.f * red[0] * invB;
            float total = noobj + obj + xy + wh + score;
            out[0] = total;
            if (out_size >= 6) {
                out[1] = noobj; out[2] = obj; out[3] = score; out[4] = xy; out[5] = wh;
            }
        }
        __syncthreads();
        for (int n = tid; n < NAA; n += NTHR) {
            g_Sce[n] = 0.f; g_cnt[n] = 0.f; g_corr[n] = 0.f;
        }
        if (tid < 8) g_acc[tid] = 0.f;
        if (tid == 0) g_done = 0u;
        __threadfence();
    }
}

extern "C" void kernel_launch(void* const* d_in, const int* in_sizes, int n_in,
                              void* d_out, int out_size) {
    const float *conf = nullptr, *pxy = nullptr, *pwh = nullptr;
    const float *cls = nullptr, *tl = nullptr, *tobj = nullptr;
    for (int i = 0; i < n_in; i++) {
        int s = in_sizes[i];
        if (s == ROWS)                   conf = (const float*)d_in[i];
        else if (s == ROWS * 2)        { if (!pxy) pxy = (const float*)d_in[i];
                                         else      pwh = (const float*)d_in[i]; }
        else if (s == ROWS * CC)         cls  = (const float*)d_in[i];
        else if (s == BATCH * MM * CC)   tl   = (const float*)d_in[i];
        else if (s == BATCH * MM * 4)    tobj = (const float*)d_in[i];
    }
    yolo_loss_kernel<<<NBLK, NTHR>>>(conf, pxy, pwh, cls, tl, tobj,
                                     (float*)d_out, out_size);
}